// round 16
// baseline (speedup 1.0000x reference)
#include <cuda_runtime.h>
#include <cuda_bf16.h>
#include <cuda_fp16.h>
#include <cstdint>

// ---------------------------------------------------------------------------
// MHConvAttention  (B=16, C=128, H=W=64, NH=8, HD=16, WIN=5, OUT=512)
// Round 15: two-stream batch pipelining (batches 0-7 / 8-15 on forked streams)
// ---------------------------------------------------------------------------
#define Bn   16
#define Cc   128
#define NHh  8
#define HDd  16
#define HW   4096
#define OUTC 512
#define BH   8                      // batches per half

__device__ __half g_s_h  [(size_t)Bn * Cc * HW];
__device__ __half g_src_h[(size_t)Bn * Cc * HW];
__device__ __half g_r1_h [(size_t)Bn * Cc * HW];
__device__ __half g_qkv_h[(size_t)Bn * 3 * Cc * HW];
__device__ float  g_pool [Bn * Cc];
__device__ __half g_wcat_h[(size_t)Bn * OUTC * 256];
__device__ __half g_qkvw_h[384 * 128];
__device__ float  g_lam2 [2][Bn * NHh * 256];
__device__ float  g_ksum2[2][Bn * NHh * 16];

// ---------------------------------------------------------------------------
__device__ __forceinline__ void mma16(float* c, const uint32_t* a, const uint32_t* b) {
    asm volatile(
        "mma.sync.aligned.m16n8k16.row.col.f32.f16.f16.f32 "
        "{%0,%1,%2,%3},{%4,%5,%6,%7},{%8,%9},{%0,%1,%2,%3};"
        : "+f"(c[0]), "+f"(c[1]), "+f"(c[2]), "+f"(c[3])
        : "r"(a[0]), "r"(a[1]), "r"(a[2]), "r"(a[3]), "r"(b[0]), "r"(b[1]));
}
__device__ __forceinline__ void ldsm4(uint32_t& r0, uint32_t& r1, uint32_t& r2, uint32_t& r3,
                                      uint32_t addr) {
    asm volatile("ldmatrix.sync.aligned.m8n8.x4.shared.b16 {%0,%1,%2,%3}, [%4];"
                 : "=r"(r0), "=r"(r1), "=r"(r2), "=r"(r3) : "r"(addr));
}
__device__ __forceinline__ void ldsm4t(uint32_t& r0, uint32_t& r1, uint32_t& r2, uint32_t& r3,
                                       uint32_t addr) {
    asm volatile("ldmatrix.sync.aligned.m8n8.x4.trans.shared.b16 {%0,%1,%2,%3}, [%4];"
                 : "=r"(r0), "=r"(r1), "=r"(r2), "=r"(r3) : "r"(addr));
}
__device__ __forceinline__ void cp16(uint32_t dst, const void* src) {
    asm volatile("cp.async.cg.shared.global [%0], [%1], 16;" :: "r"(dst), "l"(src));
}

// ---------------------------------------------------------------------------
// 1. CPE (3x3 depthwise + residual) + mean pool + fp16 emission   (per half)
// ---------------------------------------------------------------------------
__global__ __launch_bounds__(256) void cpe_pool_kernel(const float* __restrict__ src,
                                                       const float* __restrict__ cw,
                                                       int b0)
{
    const int bc = blockIdx.x + b0 * Cc;
    const int c  = bc & (Cc - 1);
    const float* sp = src     + (size_t)bc * HW;
    __half*      op = g_s_h   + (size_t)bc * HW;
    __half*      rp = g_src_h + (size_t)bc * HW;

    __shared__ float tile[64][65];
    __shared__ float wsh[9];
    __shared__ float rsum[8];

    const int t = threadIdx.x;
    if (t < 9) wsh[t] = cw[c * 9 + t];

    float psum = 0.f;
    #pragma unroll
    for (int j = 0; j < 4; j++) {
        const int idx = (t + j * 256) * 4;
        const int y = idx >> 6, x = idx & 63;
        float4 v = *(const float4*)&sp[idx];
        tile[y][x + 0] = v.x; tile[y][x + 1] = v.y;
        tile[y][x + 2] = v.z; tile[y][x + 3] = v.w;
        ((__half2*)rp)[idx / 2 + 0] = __floats2half2_rn(v.x, v.y);
        ((__half2*)rp)[idx / 2 + 1] = __floats2half2_rn(v.z, v.w);
        psum += (v.x + v.y) + (v.z + v.w);
    }
    #pragma unroll
    for (int s = 16; s; s >>= 1) psum += __shfl_xor_sync(~0u, psum, s);
    if ((t & 31) == 0) rsum[t >> 5] = psum;
    __syncthreads();
    if (t == 0) {
        float tot = 0.f;
        #pragma unroll
        for (int w = 0; w < 8; w++) tot += rsum[w];
        g_pool[bc] = tot * (1.0f / 4096.0f);
    }

    const float w00 = wsh[0], w01 = wsh[1], w02 = wsh[2];
    const float w10 = wsh[3], w11 = wsh[4], w12 = wsh[5];
    const float w20 = wsh[6], w21 = wsh[7], w22 = wsh[8];

    for (int idx = t; idx < HW; idx += 256) {
        const int y = idx >> 6, x = idx & 63;
        float acc = tile[y][x];
        const bool yt = (y > 0), yb = (y < 63), xl = (x > 0), xr = (x < 63);
        if (yt) {
            if (xl) acc += w00 * tile[y-1][x-1];
            acc += w01 * tile[y-1][x];
            if (xr) acc += w02 * tile[y-1][x+1];
        }
        if (xl) acc += w10 * tile[y][x-1];
        acc += w11 * tile[y][x];
        if (xr) acc += w12 * tile[y][x+1];
        if (yb) {
            if (xl) acc += w20 * tile[y+1][x-1];
            acc += w21 * tile[y+1][x];
            if (xr) acc += w22 * tile[y+1][x+1];
        }
        op[idx] = __float2half_rn(acc);
    }
}

// ---------------------------------------------------------------------------
// 2. Weight prep per half: wcat for 8 batches + full qkv_w cast (redundant,
//    identical values from both halves — benign)
// ---------------------------------------------------------------------------
#define WHALF (BH * OUTC * 256)
__global__ void wprep_kernel(const float* __restrict__ ow, const float* __restrict__ qw,
                             const float* __restrict__ w3, int b0)
{
    const int idx = blockIdx.x * 256 + threadIdx.x;
    if (idx < WHALF) {
        const int b   = b0 + (idx >> 17);
        const int rem = idx & 131071;
        const int cc  = rem & 255;
        float w = ow[rem];
        if (cc >= 128) {
            const int c  = cc - 128;
            const int pi = b * 128 + c;
            const float x0 = (c > 0)   ? g_pool[pi - 1] : 0.f;
            const float x1 = g_pool[pi];
            const float x2 = (c < 127) ? g_pool[pi + 1] : 0.f;
            const float z  = w3[0] * x0 + w3[1] * x1 + w3[2] * x2;
            w *= 1.0f / (1.0f + __expf(-z));
        }
        g_wcat_h[(size_t)b * OUTC * 256 + rem] = __float2half_rn(w);
    } else {
        const int j = idx - WHALF;
        if (j < 384 * 128) g_qkvw_h[j] = __float2half_rn(qw[j]);
    }
}

// ---------------------------------------------------------------------------
// fp16 tensor-core GEMM body (64x128 tile, 32x32 warp tiles, 3-stage ring)
// ---------------------------------------------------------------------------
#define ASTG  5120
#define BOFF  15360
#define BSTG  8704
#define GSMEM (BOFF + 3 * BSTG)     // 41472

template<int KTOT, typename OutT>
__device__ __forceinline__ void gemm_body_h(const __half* __restrict__ A,
                                            const __half* __restrict__ B0,
                                            const __half* __restrict__ B1,
                                            OutT* __restrict__ C)
{
    constexpr int NCH = KTOT / 32;
    extern __shared__ char dsm[];
    const int n0 = blockIdx.x * 128;
    const int m0 = blockIdx.y * 64;

    const int t = threadIdx.x;
    const int wid = t >> 5, lane = t & 31;
    const int lq = lane >> 2, lr = lane & 3;
    const int wm = (wid >> 2) * 32, wn = (wid & 3) * 32;

    float acc[2][4][4];
    #pragma unroll
    for (int i = 0; i < 2; i++)
        #pragma unroll
        for (int j = 0; j < 4; j++)
            #pragma unroll
            for (int r = 0; r < 4; r++) acc[i][j][r] = 0.f;

    const int am = t >> 2, akoff = (t & 3) * 8;
    const int bk = t >> 3, bnoff = (t & 7) * 8;
    const uint32_t dsb = (uint32_t)__cvta_generic_to_shared(dsm);

    auto loadA = [&](int stg, int c) {
        const __half* s = A + (size_t)(m0 + am) * KTOT + c * 32 + akoff;
        cp16(dsb + stg * ASTG + (am * 40 + akoff) * 2, s);
    };
    auto loadB = [&](int stg, int c) {
        const int kg = c * 32 + bk;
        const __half* bp = (KTOT == 128 || kg < 128)
                           ? B0 + (size_t)kg * HW
                           : B1 + (size_t)(kg - 128) * HW;
        uint32_t d = dsb + BOFF + stg * BSTG + (bk * 136 + bnoff) * 2;
        cp16(d,       bp + n0 + bnoff);
        cp16(d + 128, bp + n0 + bnoff + 64);
    };

    const int aLaneRow = lane & 15, aLaneCol = (lane >> 4) * 8;
    const int bLaneK   = (lane & 7) + ((lane >> 3) & 1) * 8;
    const int bLaneN   = (lane >> 4) * 8;

    loadA(0, 0); loadB(0, 0);
    asm volatile("cp.async.commit_group;");
    if (NCH > 1) { loadA(1, 1); loadB(1, 1); }
    asm volatile("cp.async.commit_group;");

    int stg = 0;
    #pragma unroll
    for (int c = 0; c < NCH; c++) {
        asm volatile("cp.async.wait_group 1;" ::: "memory");
        __syncthreads();

        if (c + 2 < NCH) {
            const int ps = (stg + 2 >= 3) ? stg - 1 : stg + 2;
            loadA(ps, c + 2); loadB(ps, c + 2);
        }
        asm volatile("cp.async.commit_group;");

        const uint32_t asb = dsb + stg * ASTG;
        const uint32_t bsb = dsb + BOFF + stg * BSTG;

        #pragma unroll
        for (int s2 = 0; s2 < 32; s2 += 16) {
            uint32_t af[2][4], bf[4][2];
            #pragma unroll
            for (int mi = 0; mi < 2; mi++) {
                const uint32_t addr = asb +
                    (uint32_t)(((wm + mi * 16 + aLaneRow) * 40 + s2 + aLaneCol) * 2);
                ldsm4(af[mi][0], af[mi][1], af[mi][2], af[mi][3], addr);
            }
            #pragma unroll
            for (int p = 0; p < 2; p++) {
                const uint32_t addr = bsb +
                    (uint32_t)(((s2 + bLaneK) * 136 + wn + p * 16 + bLaneN) * 2);
                ldsm4t(bf[2*p][0], bf[2*p][1], bf[2*p+1][0], bf[2*p+1][1], addr);
            }
            #pragma unroll
            for (int mi = 0; mi < 2; mi++)
                #pragma unroll
                for (int ni = 0; ni < 4; ni++)
                    mma16(acc[mi][ni], af[mi], bf[ni]);
        }
        stg = (stg + 1 == 3) ? 0 : stg + 1;
    }

    #pragma unroll
    for (int mi = 0; mi < 2; mi++) {
        #pragma unroll
        for (int ni = 0; ni < 4; ni++) {
            const int row = m0 + wm + mi * 16 + lq;
            const int col = n0 + wn + ni * 8 + lr * 2;
            if constexpr (sizeof(OutT) == 2) {
                *(__half2*)&C[(size_t)row * HW + col] =
                    __floats2half2_rn(acc[mi][ni][0], acc[mi][ni][1]);
                *(__half2*)&C[(size_t)(row + 8) * HW + col] =
                    __floats2half2_rn(acc[mi][ni][2], acc[mi][ni][3]);
            } else {
                __stcs((float2*)&C[(size_t)row * HW + col],
                       make_float2(acc[mi][ni][0], acc[mi][ni][1]));
                __stcs((float2*)&C[(size_t)(row + 8) * HW + col],
                       make_float2(acc[mi][ni][2], acc[mi][ni][3]));
            }
        }
    }
}

// 3. QKV GEMM (per half)
__global__ __launch_bounds__(256, 3) void gemm_qkv_tc(int b0)
{
    const int b = blockIdx.z + b0;
    gemm_body_h<128, __half>(g_qkvw_h, g_s_h + (size_t)b * Cc * HW, nullptr,
                             g_qkv_h + (size_t)b * 3 * Cc * HW);
}

// 6. out GEMM (per half)
__global__ __launch_bounds__(256, 3) void gemm_out_tc(float* __restrict__ out, int b0)
{
    const int b = blockIdx.z + b0;
    gemm_body_h<256, float>(g_wcat_h + (size_t)b * OUTC * 256,
                            g_r1_h   + (size_t)b * Cc * HW,
                            g_src_h  + (size_t)b * Cc * HW,
                            out      + (size_t)b * OUTC * HW);
}

// ---------------------------------------------------------------------------
// 4. Lambda via tensor cores, split-K x2 (per half: 64 bh-slices x 2)
// ---------------------------------------------------------------------------
__global__ __launch_bounds__(256) void lambda_mma_kernel(int b0)
{
    const int bx = blockIdx.x;
    const int bh = (bx >> 1) + b0 * NHh, half = bx & 1;
    const int b = bh >> 3, h = bh & 7;
    const __half* kb = g_qkv_h + ((size_t)b * 384 + 128 + h * 16) * HW;
    const __half* vb = g_qkv_h + ((size_t)b * 384 + 256 + h * 16) * HW;

    __shared__ __half ks[16][520];
    __shared__ __half vs[16][520];
    __shared__ float racc[8][16][16];
    __shared__ float rsum[8][16];

    const int t = threadIdx.x, wid = t >> 5, lane = t & 31;
    const int lq = lane >> 2, lr = lane & 3;

    float acc[2][4] = {};
    float se0 = 0.f, se1 = 0.f;

    const int aRow = lane & 15, aCol = (lane >> 4) * 8;
    const int bRow = (lane & 7) + ((lane >> 3) & 1) * 8;
    const int bCol = (lane >> 4) * 8;

    const uint32_t ksb = (uint32_t)__cvta_generic_to_shared(&ks[0][0]);
    const uint32_t vsb = (uint32_t)__cvta_generic_to_shared(&vs[0][0]);
    const int w0 = wid * 64;

    for (int tile = 0; tile < 4; tile++) {
        const int nbase = half * 2048 + tile * 512;
        #pragma unroll
        for (int j = 0; j < 4; j++) {
            const int s = t + j * 256;
            const int r = s >> 6, ccol = (s & 63) * 8;
            cp16(ksb + (r * 520 + ccol) * 2, kb + (size_t)r * HW + nbase + ccol);
            cp16(vsb + (r * 520 + ccol) * 2, vb + (size_t)r * HW + nbase + ccol);
        }
        asm volatile("cp.async.commit_group;");
        asm volatile("cp.async.wait_group 0;" ::: "memory");
        __syncthreads();

        #pragma unroll
        for (int kk = 0; kk < 64; kk += 16) {
            uint32_t a[4], bq[4];
            ldsm4(a[0], a[1], a[2], a[3], ksb + (aRow * 520 + w0 + kk + aCol) * 2);
            ldsm4(bq[0], bq[1], bq[2], bq[3], vsb + (bRow * 520 + w0 + kk + bCol) * 2);
            #pragma unroll
            for (int r2 = 0; r2 < 4; r2++) {
                float2 f = __half22float2(*(__half2*)&a[r2]);
                f.x = __expf(f.x); f.y = __expf(f.y);
                if ((r2 & 1) == 0) se0 += f.x + f.y; else se1 += f.x + f.y;
                *(__half2*)&a[r2] = __floats2half2_rn(f.x, f.y);
            }
            uint32_t bg0[2] = { bq[0], bq[2] };
            uint32_t bg1[2] = { bq[1], bq[3] };
            mma16(acc[0], a, bg0);
            mma16(acc[1], a, bg1);
        }
        __syncthreads();
    }

    se0 += __shfl_xor_sync(~0u, se0, 1); se0 += __shfl_xor_sync(~0u, se0, 2);
    se1 += __shfl_xor_sync(~0u, se1, 1); se1 += __shfl_xor_sync(~0u, se1, 2);
    if (lr == 0) { rsum[wid][lq] = se0; rsum[wid][lq + 8] = se1; }

    #pragma unroll
    for (int g = 0; g < 2; g++) {
        racc[wid][lq    ][g * 8 + lr * 2    ] = acc[g][0];
        racc[wid][lq    ][g * 8 + lr * 2 + 1] = acc[g][1];
        racc[wid][lq + 8][g * 8 + lr * 2    ] = acc[g][2];
        racc[wid][lq + 8][g * 8 + lr * 2 + 1] = acc[g][3];
    }
    __syncthreads();

    const int i = t >> 4, o = t & 15;
    float s = 0.f, ksum = 0.f;
    #pragma unroll
    for (int w = 0; w < 8; w++) { s += racc[w][i][o]; ksum += rsum[w][i]; }
    g_lam2[half][bh * 256 + i * 16 + o] = s;
    if (o == 0) g_ksum2[half][bh * 16 + i] = ksum;
}

// ---------------------------------------------------------------------------
// 5. result1 (per half)
// ---------------------------------------------------------------------------
__global__ __launch_bounds__(256) void result1_kernel(const float* __restrict__ relpos,
                                                      int b0)
{
    const int bh = blockIdx.z + b0 * NHh;
    const int b = bh >> 3, h = bh & 7;
    const int x0 = blockIdx.x * 16, y0 = blockIdx.y * 16;
    const __half* qb = g_qkv_h + ((size_t)b * 384 +       h * 16) * HW;
    const __half* vb = g_qkv_h + ((size_t)b * 384 + 256 + h * 16) * HW;

    __shared__ float vs[16][20][20];
    __shared__ float ls[16][16];
    __shared__ float rp[16][25];
    __shared__ float sinv[16];

    const int t = threadIdx.x;

    const float lm = g_lam2[0][bh * 256 + t] + g_lam2[1][bh * 256 + t];
    if (t < 16)
        sinv[t] = 0.25f / (g_ksum2[0][bh * 16 + t] + g_ksum2[1][bh * 16 + t]);

    for (int idx = t; idx < 400; idx += 256) rp[idx / 25][idx % 25] = relpos[idx];
    for (int idx = t; idx < 16 * 400; idx += 256) {
        const int o = idx / 400, rem = idx % 400;
        const int yy = rem / 20, xx = rem % 20;
        const int gy = y0 + yy - 2, gx = x0 + xx - 2;
        float val = 0.f;
        if ((unsigned)gy < 64u && (unsigned)gx < 64u)
            val = __half2float(vb[(size_t)o * HW + gy * 64 + gx]);
        vs[o][yy][xx] = val;
    }
    __syncthreads();
    ls[t >> 4][t & 15] = lm * sinv[t >> 4];
    __syncthreads();

    const int tx = t & 15, ty = t >> 4;
    const int n  = (y0 + ty) * 64 + (x0 + tx);

    float qreg[16];
    #pragma unroll
    for (int i = 0; i < 16; i++) qreg[i] = __half2float(qb[(size_t)i * HW + n]);

    #pragma unroll
    for (int o = 0; o < 16; o++) {
        float pos = 0.f;
        #pragma unroll
        for (int dy = 0; dy < 5; dy++)
            #pragma unroll
            for (int dx = 0; dx < 5; dx++)
                pos = fmaf(rp[o][dy * 5 + dx], vs[o][ty + dy][tx + dx], pos);
        float cont = 0.f;
        #pragma unroll
        for (int i = 0; i < 16; i++) cont = fmaf(qreg[i], ls[i][o], cont);
        g_r1_h[((size_t)bh * 16 + o) * HW + n] = __float2half_rn(cont + qreg[o] * pos);
    }
}

// ---------------------------------------------------------------------------
extern "C" void kernel_launch(void* const* d_in, const int* in_sizes, int n_in,
                              void* d_out, int out_size)
{
    const float* src      = (const float*)d_in[0];
    const float* cpe_w    = (const float*)d_in[1];
    const float* qkv_w    = (const float*)d_in[2];
    const float* rel_pos  = (const float*)d_in[3];
    const float* conv1d_w = (const float*)d_in[4];
    const float* out_w    = (const float*)d_in[5];
    float* out = (float*)d_out;

    static cudaStream_t s2 = nullptr;
    static cudaEvent_t  evFork = nullptr, evJoin = nullptr;
    if (s2 == nullptr) {
        cudaFuncSetAttribute(gemm_qkv_tc, cudaFuncAttributeMaxDynamicSharedMemorySize, GSMEM);
        cudaFuncSetAttribute(gemm_out_tc, cudaFuncAttributeMaxDynamicSharedMemorySize, GSMEM);
        cudaStreamCreateWithFlags(&s2, cudaStreamNonBlocking);
        cudaEventCreateWithFlags(&evFork, cudaEventDisableTiming);
        cudaEventCreateWithFlags(&evJoin, cudaEventDisableTiming);
    }

    const int wblocks = (WHALF + 384 * 128 + 255) / 256;

    // fork
    cudaEventRecord(evFork, 0);
    cudaStreamWaitEvent(s2, evFork, 0);

    // half A (batches 0-7) on the capture/default stream
    cpe_pool_kernel<<<BH * Cc, 256>>>(src, cpe_w, 0);
    wprep_kernel<<<wblocks, 256>>>(out_w, qkv_w, conv1d_w, 0);
    gemm_qkv_tc<<<dim3(32, 6, BH), 256, GSMEM>>>(0);
    lambda_mma_kernel<<<BH * NHh * 2, 256>>>(0);
    result1_kernel<<<dim3(4, 4, BH * NHh), 256>>>(rel_pos, 0);
    gemm_out_tc<<<dim3(32, 8, BH), 256, GSMEM>>>(out, 0);

    // half B (batches 8-15) on the forked stream
    cpe_pool_kernel<<<BH * Cc, 256, 0, s2>>>(src, cpe_w, BH);
    wprep_kernel<<<wblocks, 256, 0, s2>>>(out_w, qkv_w, conv1d_w, BH);
    gemm_qkv_tc<<<dim3(32, 6, BH), 256, GSMEM, s2>>>(BH);
    lambda_mma_kernel<<<BH * NHh * 2, 256, 0, s2>>>(BH);
    result1_kernel<<<dim3(4, 4, BH * NHh), 256, 0, s2>>>(rel_pos, BH);
    gemm_out_tc<<<dim3(32, 8, BH), 256, GSMEM, s2>>>(out, BH);

    // join
    cudaEventRecord(evJoin, s2);
    cudaStreamWaitEvent(0, evJoin, 0);
}